// round 4
// baseline (speedup 1.0000x reference)
#include <cuda_runtime.h>
#include <cuda_bf16.h>
#include <math.h>

// ---------------------------------------------------------------------------
// Problem constants
// ---------------------------------------------------------------------------
#define BB     8          // batch
#define SS     2048       // seq len
#define TT     (BB*SS)    // tokens = 16384
#define DM     256        // d_model
#define DI     512        // d_inner
#define DSTATE 16
#define DCONV  4
#define NVOCAB 256
#define LOG_VOCAB_F 5.5451774444795623f
#define RMS_EPS 1.1920928955078125e-7f

// ---------------------------------------------------------------------------
// Scratch (device globals: allocation-free per harness rules)
// ---------------------------------------------------------------------------
__device__ float g_x    [TT * DM];        // activations (residual stream)
__device__ float g_xinz [TT * 2 * DI];    // in_proj output (x_in | z)
__device__ float g_xc   [TT * DI];        // conv+silu output
__device__ float g_dt   [TT * DI];        // dt pre-activation
__device__ float g_Bm   [TT * DSTATE];    // B matrix (x_proj first half)
__device__ float g_u    [TT * DI];        // gated y before out_proj
__device__ float g_y2   [TT * DM];        // out_proj output
__device__ float g_log  [TT * NVOCAB];    // head logits
__device__ float g_ent  [TT];             // normalized entropy
__device__ int   g_pstart[BB * SS];       // patch start index per (b,p)
__device__ int   g_np    [BB];            // num patches per batch row

// ---------------------------------------------------------------------------
// Embedding lookup
// ---------------------------------------------------------------------------
__global__ void embed_kernel(const int* __restrict__ bytes,
                             const float* __restrict__ embW,
                             float* __restrict__ x) {
    int idx = blockIdx.x * blockDim.x + threadIdx.x;   // over TT*DM
    int t = idx >> 8;          // /256
    int d = idx & 255;
    x[idx] = embW[bytes[t] * DM + d];
}

// ---------------------------------------------------------------------------
// Tiled fp32 GEMM:  C[M,N] = A[M,K] @ W[K,N]   (all row-major, strides given)
// blockDim = 256 threads, each computes TM x TN outputs.
// ---------------------------------------------------------------------------
template<int BM, int BN, int BK, int TM, int TN>
__global__ void gemm_kernel(const float* __restrict__ A, int lda,
                            const float* __restrict__ W, int ldw,
                            float* __restrict__ C, int ldc,
                            int K) {
    __shared__ float As[BK][BM + 4];
    __shared__ float Ws[BK][BN];

    const int tid = threadIdx.x;
    const int nTx = BN / TN;
    const int tx  = tid % nTx;
    const int ty  = tid / nTx;
    const int rowBase = blockIdx.y * BM;
    const int colBase = blockIdx.x * BN;

    float acc[TM][TN];
    #pragma unroll
    for (int i = 0; i < TM; i++)
        #pragma unroll
        for (int j = 0; j < TN; j++) acc[i][j] = 0.f;

    for (int k0 = 0; k0 < K; k0 += BK) {
        #pragma unroll
        for (int i = tid; i < BM * BK; i += 256) {
            int m  = i / BK;
            int kk = i % BK;
            As[kk][m] = A[(size_t)(rowBase + m) * lda + k0 + kk];
        }
        #pragma unroll
        for (int i = tid; i < BK * BN; i += 256) {
            int kk = i / BN;
            int n  = i % BN;
            Ws[kk][n] = W[(size_t)(k0 + kk) * ldw + colBase + n];
        }
        __syncthreads();

        #pragma unroll
        for (int kk = 0; kk < BK; kk++) {
            float a[TM], b[TN];
            #pragma unroll
            for (int i = 0; i < TM; i++) a[i] = As[kk][ty * TM + i];
            #pragma unroll
            for (int j = 0; j < TN; j++) b[j] = Ws[kk][tx * TN + j];
            #pragma unroll
            for (int i = 0; i < TM; i++)
                #pragma unroll
                for (int j = 0; j < TN; j++)
                    acc[i][j] = fmaf(a[i], b[j], acc[i][j]);
        }
        __syncthreads();
    }

    #pragma unroll
    for (int i = 0; i < TM; i++)
        #pragma unroll
        for (int j = 0; j < TN; j++)
            C[(size_t)(rowBase + ty * TM + i) * ldc + colBase + tx * TN + j] = acc[i][j];
}

// ---------------------------------------------------------------------------
// Causal depthwise conv (width 4) + bias + silu.  x_in = first DI cols of xinz.
// ---------------------------------------------------------------------------
__global__ void conv_silu_kernel(const float* __restrict__ xinz,
                                 const float* __restrict__ cw,   // [DI, DCONV]
                                 const float* __restrict__ cb,   // [DI]
                                 float* __restrict__ xc) {
    int idx = blockIdx.x * blockDim.x + threadIdx.x;   // over TT*DI
    int t = idx / DI;
    int d = idx - t * DI;
    int b = t / SS;
    int s = t - b * SS;

    float acc = cb[d];
    #pragma unroll
    for (int k = 0; k < DCONV; k++) {
        int ss = s - (DCONV - 1) + k;
        if (ss >= 0)
            acc = fmaf(cw[d * DCONV + k],
                       xinz[(size_t)(b * SS + ss) * (2 * DI) + d], acc);
    }
    // silu
    xc[idx] = acc / (1.f + expf(-acc));
}

// ---------------------------------------------------------------------------
// Fused Mamba pointwise core:
//   dt = softplus(dtpre + dtb)
//   y  = dt*xc*sum_n exp(-exp(A_log[d,n])*dt)*B[n] + D*xc
//   u  = y * silu(z)
// negA stored TRANSPOSED in smem: [n][d] -> conflict-free lane reads.
// ---------------------------------------------------------------------------
#define EW_TOKS 8
__global__ void mamba_ew_kernel(const float* __restrict__ dtpre,
                                const float* __restrict__ xc,
                                const float* __restrict__ xinz,
                                const float* __restrict__ Bmat,
                                const float* __restrict__ Alog,  // [DI, DSTATE]
                                const float* __restrict__ dtb,   // [DI]
                                const float* __restrict__ Dp,    // [DI]
                                float* __restrict__ u) {
    __shared__ float negAT[DSTATE][DI];   // 32 KB
    __shared__ float sdtb[DI];
    __shared__ float sD[DI];
    __shared__ float sB[DSTATE];

    const int tid = threadIdx.x;
    for (int i = tid; i < DI * DSTATE; i += 256) {
        int d = i / DSTATE, n = i % DSTATE;
        negAT[n][d] = -expf(Alog[i]);
    }
    for (int i = tid; i < DI; i += 256) { sdtb[i] = dtb[i]; sD[i] = Dp[i]; }
    __syncthreads();

    for (int tok = 0; tok < EW_TOKS; tok++) {
        int t = blockIdx.x * EW_TOKS + tok;
        if (tid < DSTATE) sB[tid] = Bmat[t * DSTATE + tid];
        __syncthreads();

        #pragma unroll
        for (int rep = 0; rep < 2; rep++) {
            int d = tid + rep * 256;
            float v   = dtpre[(size_t)t * DI + d] + sdtb[d];
            // stable softplus = max(v,0) + log1p(exp(-|v|))
            float dtv = fmaxf(v, 0.f) + log1pf(expf(-fabsf(v)));
            float xcv = xc[(size_t)t * DI + d];
            float accn = 0.f;
            #pragma unroll
            for (int n = 0; n < DSTATE; n++)
                accn = fmaf(expf(negAT[n][d] * dtv), sB[n], accn);
            float yv = dtv * xcv * accn + sD[d] * xcv;
            float zv = xinz[(size_t)t * (2 * DI) + DI + d];
            u[(size_t)t * DI + d] = yv * (zv / (1.f + expf(-zv)));
        }
        __syncthreads();
    }
}

// ---------------------------------------------------------------------------
// Residual add + RMSNorm (in-place into x). 1 block per token, 256 threads.
// ---------------------------------------------------------------------------
__global__ void rmsnorm_add_kernel(float* __restrict__ x,
                                   const float* __restrict__ y2,
                                   const float* __restrict__ nw) {
    __shared__ float red[256];
    int t = blockIdx.x;
    int d = threadIdx.x;
    float v = y2[(size_t)t * DM + d] + x[(size_t)t * DM + d];
    red[d] = v * v;
    __syncthreads();
    for (int s = 128; s > 0; s >>= 1) {
        if (d < s) red[d] += red[d + s];
        __syncthreads();
    }
    float scale = rsqrtf(red[0] * (1.f / DM) + RMS_EPS);
    x[(size_t)t * DM + d] = v * scale * nw[d];
}

// ---------------------------------------------------------------------------
// Entropy of softmax(logits) per token, normalized by log(VOCAB).
// ---------------------------------------------------------------------------
__global__ void entropy_kernel(const float* __restrict__ logits,
                               float* __restrict__ ent) {
    __shared__ float red[256];
    int t = blockIdx.x;
    int d = threadIdx.x;
    float l = logits[(size_t)t * NVOCAB + d];

    red[d] = l;
    __syncthreads();
    for (int s = 128; s > 0; s >>= 1) {
        if (d < s) red[d] = fmaxf(red[d], red[d + s]);
        __syncthreads();
    }
    float m = red[0];
    __syncthreads();

    float e = expf(l - m);
    red[d] = e;
    __syncthreads();
    for (int s = 128; s > 0; s >>= 1) {
        if (d < s) red[d] += red[d + s];
        __syncthreads();
    }
    float Z = red[0];
    __syncthreads();

    red[d] = e * l;
    __syncthreads();
    for (int s = 128; s > 0; s >>= 1) {
        if (d < s) red[d] += red[d + s];
        __syncthreads();
    }
    float sumel = red[0];

    if (d == 0) {
        float lse = m + logf(Z);
        float H = lse - sumel / Z;
        ent[t] = H / LOG_VOCAB_F;
    }
}

// ---------------------------------------------------------------------------
// Sequential boundary automaton per batch row. Also emits byte_to_patch (as
// float, straight into the output buffer) and patch_start/num_patches.
// ---------------------------------------------------------------------------
__global__ void boundary_kernel(const float* __restrict__ ent,
                                int* __restrict__ pstart,
                                int* __restrict__ np,
                                float* __restrict__ out_b2p) {
    __shared__ float se[SS];
    int b = blockIdx.x;
    for (int i = threadIdx.x; i < SS; i += blockDim.x)
        se[i] = ent[b * SS + i];
    __syncthreads();

    if (threadIdx.x == 0) {
        int size = 1;
        int p = 0;
        pstart[b * SS + 0] = 0;
        out_b2p[b * SS + 0] = 0.f;
        for (int s = 1; s < SS; s++) {
            float e = se[s];
            bool nb = (e > 0.5f) || (size >= 8);   // MIN_P=1 always satisfied
            if (nb) { p++; pstart[b * SS + p] = s; size = 1; }
            else    { size++; }
            out_b2p[b * SS + s] = (float)p;
        }
        np[b] = p + 1;
    }
}

// ---------------------------------------------------------------------------
// Patch mean pooling: 1 block per (b, p); patches are contiguous byte ranges.
// ---------------------------------------------------------------------------
__global__ void pool_kernel(const float* __restrict__ be,
                            const int* __restrict__ pstart,
                            const int* __restrict__ np,
                            float* __restrict__ out_emb,
                            float* __restrict__ out_len) {
    int blk = blockIdx.x;
    int b = blk / SS;
    int p = blk - b * SS;
    int d = threadIdx.x;
    int npb = np[b];

    if (p < npb) {
        int s0 = pstart[b * SS + p];
        int s1 = (p + 1 < npb) ? pstart[b * SS + p + 1] : SS;
        float sum = 0.f;
        for (int s = s0; s < s1; s++)
            sum += be[(size_t)(b * SS + s) * DM + d];
        out_emb[(size_t)blk * DM + d] = sum / (float)(s1 - s0);
        if (d == 0) out_len[blk] = (float)(s1 - s0);
    } else {
        out_emb[(size_t)blk * DM + d] = 0.f;
        if (d == 0) out_len[blk] = 0.f;
    }
}

// ---------------------------------------------------------------------------
// Launch
// ---------------------------------------------------------------------------
extern "C" void kernel_launch(void* const* d_in, const int* in_sizes, int n_in,
                              void* d_out, int out_size) {
    const int*   bytes = (const int*)  d_in[0];
    const float* be    = (const float*)d_in[1];
    const float* embW  = (const float*)d_in[2];
    const float* inW   = (const float*)d_in[3];
    const float* cw    = (const float*)d_in[4];
    const float* cb    = (const float*)d_in[5];
    const float* xpW   = (const float*)d_in[6];
    const float* dtW   = (const float*)d_in[7];
    const float* dtb   = (const float*)d_in[8];
    const float* Alog  = (const float*)d_in[9];
    const float* Dp    = (const float*)d_in[10];
    const float* outW  = (const float*)d_in[11];
    const float* nw    = (const float*)d_in[12];
    const float* headW = (const float*)d_in[13];
    float* out = (float*)d_out;

    static float *px=nullptr, *pxinz, *pxc, *pdt, *pB, *pu, *py2, *plog, *pent;
    static int *ppstart, *pnp;
    if (!px) {
        cudaGetSymbolAddress((void**)&px,     g_x);
        cudaGetSymbolAddress((void**)&pxinz,  g_xinz);
        cudaGetSymbolAddress((void**)&pxc,    g_xc);
        cudaGetSymbolAddress((void**)&pdt,    g_dt);
        cudaGetSymbolAddress((void**)&pB,     g_Bm);
        cudaGetSymbolAddress((void**)&pu,     g_u);
        cudaGetSymbolAddress((void**)&py2,    g_y2);
        cudaGetSymbolAddress((void**)&plog,   g_log);
        cudaGetSymbolAddress((void**)&pent,   g_ent);
        cudaGetSymbolAddress((void**)&ppstart,g_pstart);
        cudaGetSymbolAddress((void**)&pnp,    g_np);
    }

    // 1) embedding
    embed_kernel<<<TT * DM / 256, 256>>>(bytes, embW, px);

    // 2) two mamba blocks
    for (int l = 0; l < 2; l++) {
        // x @ in_proj  -> xinz  (M=TT, N=1024, K=256)
        gemm_kernel<128,64,16,8,4><<<dim3(1024/64, TT/128), 256>>>(
            px, DM, inW + (size_t)l * DM * 2 * DI, 2 * DI, pxinz, 2 * DI, DM);
        // depthwise conv + silu
        conv_silu_kernel<<<TT * DI / 256, 256>>>(
            pxinz, cw + (size_t)l * DI * DCONV, cb + (size_t)l * DI, pxc);
        // xc @ dt_w -> dtpre  (N=512, K=512)
        gemm_kernel<128,64,16,8,4><<<dim3(512/64, TT/128), 256>>>(
            pxc, DI, dtW + (size_t)l * DI * DI, DI, pdt, DI, DI);
        // xc @ x_proj[:, :16] -> Bmat  (N=16, K=512, ldw=32)
        gemm_kernel<64,16,32,4,1><<<dim3(1, TT/64), 256>>>(
            pxc, DI, xpW + (size_t)l * DI * 2 * DSTATE, 2 * DSTATE, pB, DSTATE, DI);
        // fused pointwise core -> u
        mamba_ew_kernel<<<TT / EW_TOKS, 256>>>(
            pdt, pxc, pxinz, pB,
            Alog + (size_t)l * DI * DSTATE, dtb + (size_t)l * DI,
            Dp + (size_t)l * DI, pu);
        // u @ out_w -> y2  (N=256, K=512)
        gemm_kernel<128,64,16,8,4><<<dim3(256/64, TT/128), 256>>>(
            pu, DI, outW + (size_t)l * DI * DM, DM, py2, DM, DI);
        // residual + rmsnorm (in-place x)
        rmsnorm_add_kernel<<<TT, 256>>>(px, py2, nw + (size_t)l * DM);
    }

    // 3) head + entropy
    gemm_kernel<128,64,16,8,4><<<dim3(NVOCAB/64, TT/128), 256>>>(
        px, DM, headW, NVOCAB, plog, NVOCAB, DM);
    entropy_kernel<<<TT, 256>>>(plog, pent);

    // 4) boundaries (writes byte_to_patch floats straight into d_out tail)
    boundary_kernel<<<BB, 256>>>(pent, ppstart, pnp, out + (size_t)TT * DM + TT);

    // 5) patch pooling (patch_embeddings + patch_lengths)
    pool_kernel<<<BB * SS, 256>>>(be, ppstart, pnp, out, out + (size_t)TT * DM);
}

// round 5
// speedup vs baseline: 2.9774x; 2.9774x over previous
#include <cuda_runtime.h>
#include <cuda_bf16.h>
#include <math.h>
#include <stdint.h>

// ---------------------------------------------------------------------------
// Problem constants
// ---------------------------------------------------------------------------
#define BB     8          // batch
#define SS     2048       // seq len
#define TT     (BB*SS)    // tokens = 16384
#define DM     256        // d_model
#define DI     512        // d_inner
#define DSTATE 16
#define DCONV  4
#define NVOCAB 256
#define LOG_VOCAB_F 5.5451774444795623f
#define RMS_EPS 1.1920928955078125e-7f

typedef __nv_bfloat16 bf16;

// ---------------------------------------------------------------------------
// Scratch (device globals: allocation-free per harness rules)
// ---------------------------------------------------------------------------
__device__ float g_x    [TT * DM];        // residual stream fp32
__device__ bf16  g_xh   [TT * DM];        // residual stream bf16 (GEMM input)
__device__ float g_xinz [TT * 2 * DI];    // in_proj output (x_in | z) fp32
__device__ bf16  g_xch  [TT * DI];        // conv+silu output bf16
__device__ float g_dt   [TT * DI];        // dt pre-activation fp32
__device__ float g_Bm   [TT * DSTATE];    // B matrix
__device__ bf16  g_uh   [TT * DI];        // gated y bf16 (GEMM input)
__device__ float g_y2   [TT * DM];        // out_proj output
__device__ float g_log  [TT * NVOCAB];    // head logits
__device__ float g_ent  [TT];             // normalized entropy
__device__ int   g_pstart[BB * SS];
__device__ int   g_np    [BB];

// bf16 transposed weights [N,K] row-major, all packed in one buffer
//   in_proj: 2 x 1024x256   @ 0
//   dt:      2 x 512x512    @ 524288
//   out:     2 x 256x512    @ 1048576
//   head:    1 x 256x256    @ 1310720
#define WOFF_IN(l)   ((size_t)(l) * 1024 * 256)
#define WOFF_DT(l)   (524288u  + (size_t)(l) * 512 * 512)
#define WOFF_OUT(l)  (1048576u + (size_t)(l) * 256 * 512)
#define WOFF_HEAD    (1310720u)
__device__ bf16 g_wbf[1376256];

// ---------------------------------------------------------------------------
// Weight prep: fp32 [K,N] -> bf16 [N,K], tiled smem transpose (coalesced both ways)
// grid (N/32, K/32), 256 threads
// ---------------------------------------------------------------------------
__global__ void wprep_kernel(const float* __restrict__ W, bf16* __restrict__ out,
                             int K, int N) {
    __shared__ float tile[32][33];
    int nb = blockIdx.x * 32, kb = blockIdx.y * 32;
    int tx = threadIdx.x & 31, ty = threadIdx.x >> 5;   // ty 0..7
    #pragma unroll
    for (int r = ty; r < 32; r += 8)
        tile[r][tx] = W[(size_t)(kb + r) * N + nb + tx];
    __syncthreads();
    #pragma unroll
    for (int r = ty; r < 32; r += 8)
        out[(size_t)(nb + r) * K + kb + tx] = __float2bfloat16_rn(tile[tx][r]);
}

// ---------------------------------------------------------------------------
// Embedding lookup (fp32 + bf16)
// ---------------------------------------------------------------------------
__global__ void embed_kernel(const int* __restrict__ bytes,
                             const float* __restrict__ embW,
                             float* __restrict__ x, bf16* __restrict__ xh) {
    int idx = blockIdx.x * blockDim.x + threadIdx.x;   // over TT*DM
    int t = idx >> 8;
    int d = idx & 255;
    float v = embW[bytes[t] * DM + d];
    x[idx] = v;
    xh[idx] = __float2bfloat16_rn(v);
}

// ---------------------------------------------------------------------------
// bf16 tensor-core GEMM: C[M,N] (fp32) = A[M,K](bf16 row-major) @ Bt[N,K]^T
// Block tile 128x64x32, 256 threads (8 warps = 4x2), cp.async double buffer.
// ---------------------------------------------------------------------------
#define GBM 128
#define GBN 64
#define GBK 32
#define ASTR 40   // BK + 8 halves, row stride (80B, 16B-aligned)
#define BSTR 40

__device__ __forceinline__ void cp_async16(void* smem, const void* gmem) {
    uint32_t s = (uint32_t)__cvta_generic_to_shared(smem);
    asm volatile("cp.async.cg.shared.global [%0], [%1], 16;" :: "r"(s), "l"(gmem));
}
__device__ __forceinline__ uint32_t ld32h(const bf16* p) {
    return *reinterpret_cast<const uint32_t*>(p);
}

__global__ void __launch_bounds__(256)
mma_gemm_kernel(const bf16* __restrict__ A, int lda,
                const bf16* __restrict__ Bt, int ldb,
                float* __restrict__ C, int ldc, int K) {
    __shared__ __align__(16) bf16 sA[2][GBM * ASTR];
    __shared__ __align__(16) bf16 sB[2][GBN * BSTR];

    const int tid  = threadIdx.x;
    const int lane = tid & 31;
    const int g    = lane >> 2;       // 0..7
    const int tg   = lane & 3;        // 0..3
    const int warp = tid >> 5;        // 0..7
    const int wm   = warp & 3;        // 4 warp rows
    const int wn   = warp >> 2;       // 2 warp cols
    const int mBase = wm * 32;
    const int nBase = wn * 32;
    const int rowBase = blockIdx.y * GBM;
    const int colBase = blockIdx.x * GBN;

    // cp.async chunk mapping
    const int aRow = tid >> 2, aKc = tid & 3;     // +256 for second chunk
    const int bRow = tid >> 2, bKc = tid & 3;

    const bf16* Ab = A + (size_t)rowBase * lda;
    const bf16* Bb = Bt + (size_t)colBase * ldb;

    float acc[2][4][4];
    #pragma unroll
    for (int mi = 0; mi < 2; mi++)
        #pragma unroll
        for (int ni = 0; ni < 4; ni++)
            #pragma unroll
            for (int c = 0; c < 4; c++) acc[mi][ni][c] = 0.f;

    const int nIter = K / GBK;

    // prologue: stage 0
    {
        cp_async16(&sA[0][aRow * ASTR + aKc * 8],        Ab + (size_t)aRow * lda + aKc * 8);
        cp_async16(&sA[0][(aRow + 64) * ASTR + aKc * 8], Ab + (size_t)(aRow + 64) * lda + aKc * 8);
        cp_async16(&sB[0][bRow * BSTR + bKc * 8],        Bb + (size_t)bRow * ldb + bKc * 8);
        asm volatile("cp.async.commit_group;");
    }

    for (int it = 0; it < nIter; ++it) {
        if (it + 1 < nIter) {
            int st = (it + 1) & 1;
            int k0 = (it + 1) * GBK;
            cp_async16(&sA[st][aRow * ASTR + aKc * 8],        Ab + (size_t)aRow * lda + k0 + aKc * 8);
            cp_async16(&sA[st][(aRow + 64) * ASTR + aKc * 8], Ab + (size_t)(aRow + 64) * lda + k0 + aKc * 8);
            cp_async16(&sB[st][bRow * BSTR + bKc * 8],        Bb + (size_t)bRow * ldb + k0 + bKc * 8);
            asm volatile("cp.async.commit_group;");
            asm volatile("cp.async.wait_group 1;");
        } else {
            asm volatile("cp.async.wait_group 0;");
        }
        __syncthreads();

        const int buf = it & 1;
        const bf16* As = sA[buf];
        const bf16* Bs = sB[buf];

        #pragma unroll
        for (int ks = 0; ks < 2; ks++) {
            uint32_t af[2][4], bfr[4][2];
            #pragma unroll
            for (int mi = 0; mi < 2; mi++) {
                const bf16* ap = As + (mBase + mi * 16 + g) * ASTR + ks * 16 + tg * 2;
                af[mi][0] = ld32h(ap);
                af[mi][1] = ld32h(ap + 8 * ASTR);
                af[mi][2] = ld32h(ap + 8);
                af[mi][3] = ld32h(ap + 8 * ASTR + 8);
            }
            #pragma unroll
            for (int ni = 0; ni < 4; ni++) {
                const bf16* bp = Bs + (nBase + ni * 8 + g) * BSTR + ks * 16 + tg * 2;
                bfr[ni][0] = ld32h(bp);
                bfr[ni][1] = ld32h(bp + 8);
            }
            #pragma unroll
            for (int mi = 0; mi < 2; mi++)
                #pragma unroll
                for (int ni = 0; ni < 4; ni++) {
                    asm volatile(
                        "mma.sync.aligned.m16n8k16.row.col.f32.bf16.bf16.f32 "
                        "{%0,%1,%2,%3},{%4,%5,%6,%7},{%8,%9},{%0,%1,%2,%3};"
                        : "+f"(acc[mi][ni][0]), "+f"(acc[mi][ni][1]),
                          "+f"(acc[mi][ni][2]), "+f"(acc[mi][ni][3])
                        : "r"(af[mi][0]), "r"(af[mi][1]), "r"(af[mi][2]), "r"(af[mi][3]),
                          "r"(bfr[ni][0]), "r"(bfr[ni][1]));
                }
        }
        __syncthreads();
    }

    // epilogue
    #pragma unroll
    for (int mi = 0; mi < 2; mi++)
        #pragma unroll
        for (int ni = 0; ni < 4; ni++) {
            int row0 = rowBase + mBase + mi * 16 + g;
            int col  = colBase + nBase + ni * 8 + tg * 2;
            *reinterpret_cast<float2*>(&C[(size_t)row0 * ldc + col]) =
                make_float2(acc[mi][ni][0], acc[mi][ni][1]);
            *reinterpret_cast<float2*>(&C[(size_t)(row0 + 8) * ldc + col]) =
                make_float2(acc[mi][ni][2], acc[mi][ni][3]);
        }
}

// ---------------------------------------------------------------------------
// Small SIMT GEMM (bf16 A, fp32 W): used only for x_proj (N=16, K=512)
// ---------------------------------------------------------------------------
template<int BM, int BN, int BK, int TM, int TN>
__global__ void gemm_small_kernel(const bf16* __restrict__ A, int lda,
                                  const float* __restrict__ W, int ldw,
                                  float* __restrict__ C, int ldc, int K) {
    __shared__ float As[BK][BM + 4];
    __shared__ float Ws[BK][BN];

    const int tid = threadIdx.x;
    const int nTx = BN / TN;
    const int tx  = tid % nTx;
    const int ty  = tid / nTx;
    const int rowBase = blockIdx.y * BM;
    const int colBase = blockIdx.x * BN;

    float acc[TM][TN];
    #pragma unroll
    for (int i = 0; i < TM; i++)
        #pragma unroll
        for (int j = 0; j < TN; j++) acc[i][j] = 0.f;

    for (int k0 = 0; k0 < K; k0 += BK) {
        for (int i = tid; i < BM * BK; i += 256) {
            int m  = i / BK;
            int kk = i % BK;
            As[kk][m] = __bfloat162float(A[(size_t)(rowBase + m) * lda + k0 + kk]);
        }
        for (int i = tid; i < BK * BN; i += 256) {
            int kk = i / BN;
            int n  = i % BN;
            Ws[kk][n] = W[(size_t)(k0 + kk) * ldw + colBase + n];
        }
        __syncthreads();
        #pragma unroll
        for (int kk = 0; kk < BK; kk++) {
            float a[TM], b[TN];
            #pragma unroll
            for (int i = 0; i < TM; i++) a[i] = As[kk][ty * TM + i];
            #pragma unroll
            for (int j = 0; j < TN; j++) b[j] = Ws[kk][tx * TN + j];
            #pragma unroll
            for (int i = 0; i < TM; i++)
                #pragma unroll
                for (int j = 0; j < TN; j++)
                    acc[i][j] = fmaf(a[i], b[j], acc[i][j]);
        }
        __syncthreads();
    }
    #pragma unroll
    for (int i = 0; i < TM; i++)
        #pragma unroll
        for (int j = 0; j < TN; j++)
            C[(size_t)(rowBase + ty * TM + i) * ldc + colBase + tx * TN + j] = acc[i][j];
}

// ---------------------------------------------------------------------------
// Causal depthwise conv (width 4) + bias + silu -> bf16 xc
// ---------------------------------------------------------------------------
__global__ void conv_silu_kernel(const float* __restrict__ xinz,
                                 const float* __restrict__ cw,
                                 const float* __restrict__ cb,
                                 bf16* __restrict__ xch) {
    int idx = blockIdx.x * blockDim.x + threadIdx.x;   // over TT*DI
    int t = idx / DI;
    int d = idx - t * DI;
    int b = t / SS;
    int s = t - b * SS;

    float acc = cb[d];
    #pragma unroll
    for (int k = 0; k < DCONV; k++) {
        int ss = s - (DCONV - 1) + k;
        if (ss >= 0)
            acc = fmaf(cw[d * DCONV + k],
                       xinz[(size_t)(b * SS + ss) * (2 * DI) + d], acc);
    }
    float v = acc / (1.f + expf(-acc));
    xch[idx] = __float2bfloat16_rn(v);
}

// ---------------------------------------------------------------------------
// Fused Mamba pointwise core (xc bf16 in, u bf16 out)
// ---------------------------------------------------------------------------
#define EW_TOKS 8
__global__ void mamba_ew_kernel(const float* __restrict__ dtpre,
                                const bf16* __restrict__ xch,
                                const float* __restrict__ xinz,
                                const float* __restrict__ Bmat,
                                const float* __restrict__ Alog,
                                const float* __restrict__ dtb,
                                const float* __restrict__ Dp,
                                bf16* __restrict__ uh) {
    __shared__ float negAT[DSTATE][DI];
    __shared__ float sdtb[DI];
    __shared__ float sD[DI];
    __shared__ float sB[DSTATE];

    const int tid = threadIdx.x;
    for (int i = tid; i < DI * DSTATE; i += 256) {
        int d = i / DSTATE, n = i % DSTATE;
        negAT[n][d] = -expf(Alog[i]);
    }
    for (int i = tid; i < DI; i += 256) { sdtb[i] = dtb[i]; sD[i] = Dp[i]; }
    __syncthreads();

    for (int tok = 0; tok < EW_TOKS; tok++) {
        int t = blockIdx.x * EW_TOKS + tok;
        if (tid < DSTATE) sB[tid] = Bmat[t * DSTATE + tid];
        __syncthreads();

        #pragma unroll
        for (int rep = 0; rep < 2; rep++) {
            int d = tid + rep * 256;
            float v   = dtpre[(size_t)t * DI + d] + sdtb[d];
            float dtv = fmaxf(v, 0.f) + log1pf(expf(-fabsf(v)));
            float xcv = __bfloat162float(xch[(size_t)t * DI + d]);
            float accn = 0.f;
            #pragma unroll
            for (int n = 0; n < DSTATE; n++)
                accn = fmaf(expf(negAT[n][d] * dtv), sB[n], accn);
            float yv = dtv * xcv * accn + sD[d] * xcv;
            float zv = xinz[(size_t)t * (2 * DI) + DI + d];
            uh[(size_t)t * DI + d] = __float2bfloat16_rn(yv * (zv / (1.f + expf(-zv))));
        }
        __syncthreads();
    }
}

// ---------------------------------------------------------------------------
// Residual add + RMSNorm (in-place into x, also writes bf16 copy)
// ---------------------------------------------------------------------------
__global__ void rmsnorm_add_kernel(float* __restrict__ x,
                                   bf16* __restrict__ xh,
                                   const float* __restrict__ y2,
                                   const float* __restrict__ nw) {
    __shared__ float red[256];
    int t = blockIdx.x;
    int d = threadIdx.x;
    float v = y2[(size_t)t * DM + d] + x[(size_t)t * DM + d];
    red[d] = v * v;
    __syncthreads();
    for (int s = 128; s > 0; s >>= 1) {
        if (d < s) red[d] += red[d + s];
        __syncthreads();
    }
    float scale = rsqrtf(red[0] * (1.f / DM) + RMS_EPS);
    float o = v * scale * nw[d];
    x[(size_t)t * DM + d] = o;
    xh[(size_t)t * DM + d] = __float2bfloat16_rn(o);
}

// ---------------------------------------------------------------------------
// Entropy of softmax(logits), normalized
// ---------------------------------------------------------------------------
__global__ void entropy_kernel(const float* __restrict__ logits,
                               float* __restrict__ ent) {
    __shared__ float red[256];
    int t = blockIdx.x;
    int d = threadIdx.x;
    float l = logits[(size_t)t * NVOCAB + d];

    red[d] = l;
    __syncthreads();
    for (int s = 128; s > 0; s >>= 1) {
        if (d < s) red[d] = fmaxf(red[d], red[d + s]);
        __syncthreads();
    }
    float m = red[0];
    __syncthreads();

    float e = expf(l - m);
    red[d] = e;
    __syncthreads();
    for (int s = 128; s > 0; s >>= 1) {
        if (d < s) red[d] += red[d + s];
        __syncthreads();
    }
    float Z = red[0];
    __syncthreads();

    red[d] = e * l;
    __syncthreads();
    for (int s = 128; s > 0; s >>= 1) {
        if (d < s) red[d] += red[d + s];
        __syncthreads();
    }
    float sumel = red[0];

    if (d == 0) {
        float lse = m + logf(Z);
        float H = lse - sumel / Z;
        ent[t] = H / LOG_VOCAB_F;
    }
}

// ---------------------------------------------------------------------------
// Sequential boundary automaton per batch row
// ---------------------------------------------------------------------------
__global__ void boundary_kernel(const float* __restrict__ ent,
                                int* __restrict__ pstart,
                                int* __restrict__ np,
                                float* __restrict__ out_b2p) {
    __shared__ float se[SS];
    int b = blockIdx.x;
    for (int i = threadIdx.x; i < SS; i += blockDim.x)
        se[i] = ent[b * SS + i];
    __syncthreads();

    if (threadIdx.x == 0) {
        int size = 1;
        int p = 0;
        pstart[b * SS + 0] = 0;
        out_b2p[b * SS + 0] = 0.f;
        for (int s = 1; s < SS; s++) {
            float e = se[s];
            bool nb = (e > 0.5f) || (size >= 8);
            if (nb) { p++; pstart[b * SS + p] = s; size = 1; }
            else    { size++; }
            out_b2p[b * SS + s] = (float)p;
        }
        np[b] = p + 1;
    }
}

// ---------------------------------------------------------------------------
// Patch mean pooling
// ---------------------------------------------------------------------------
__global__ void pool_kernel(const float* __restrict__ be,
                            const int* __restrict__ pstart,
                            const int* __restrict__ np,
                            float* __restrict__ out_emb,
                            float* __restrict__ out_len) {
    int blk = blockIdx.x;
    int b = blk / SS;
    int p = blk - b * SS;
    int d = threadIdx.x;
    int npb = np[b];

    if (p < npb) {
        int s0 = pstart[b * SS + p];
        int s1 = (p + 1 < npb) ? pstart[b * SS + p + 1] : SS;
        float sum = 0.f;
        for (int s = s0; s < s1; s++)
            sum += be[(size_t)(b * SS + s) * DM + d];
        out_emb[(size_t)blk * DM + d] = sum / (float)(s1 - s0);
        if (d == 0) out_len[blk] = (float)(s1 - s0);
    } else {
        out_emb[(size_t)blk * DM + d] = 0.f;
        if (d == 0) out_len[blk] = 0.f;
    }
}

// ---------------------------------------------------------------------------
// Launch
// ---------------------------------------------------------------------------
extern "C" void kernel_launch(void* const* d_in, const int* in_sizes, int n_in,
                              void* d_out, int out_size) {
    const int*   bytes = (const int*)  d_in[0];
    const float* be    = (const float*)d_in[1];
    const float* embW  = (const float*)d_in[2];
    const float* inW   = (const float*)d_in[3];
    const float* cw    = (const float*)d_in[4];
    const float* cb    = (const float*)d_in[5];
    const float* xpW   = (const float*)d_in[6];
    const float* dtW   = (const float*)d_in[7];
    const float* dtb   = (const float*)d_in[8];
    const float* Alog  = (const float*)d_in[9];
    const float* Dp    = (const float*)d_in[10];
    const float* outW  = (const float*)d_in[11];
    const float* nw    = (const float*)d_in[12];
    const float* headW = (const float*)d_in[13];
    float* out = (float*)d_out;

    static float *px=nullptr, *pxinz, *pdt, *pB, *py2, *plog, *pent;
    static bf16 *pxh, *pxch, *puh, *pwbf;
    static int *ppstart, *pnp;
    if (!px) {
        cudaGetSymbolAddress((void**)&px,     g_x);
        cudaGetSymbolAddress((void**)&pxh,    g_xh);
        cudaGetSymbolAddress((void**)&pxinz,  g_xinz);
        cudaGetSymbolAddress((void**)&pxch,   g_xch);
        cudaGetSymbolAddress((void**)&pdt,    g_dt);
        cudaGetSymbolAddress((void**)&pB,     g_Bm);
        cudaGetSymbolAddress((void**)&puh,    g_uh);
        cudaGetSymbolAddress((void**)&py2,    g_y2);
        cudaGetSymbolAddress((void**)&plog,   g_log);
        cudaGetSymbolAddress((void**)&pent,   g_ent);
        cudaGetSymbolAddress((void**)&pwbf,   g_wbf);
        cudaGetSymbolAddress((void**)&ppstart,g_pstart);
        cudaGetSymbolAddress((void**)&pnp,    g_np);
    }

    // 0) weight prep (bf16 transposed copies)
    for (int l = 0; l < 2; l++) {
        wprep_kernel<<<dim3(1024/32, 256/32), 256>>>(
            inW + (size_t)l * DM * 2 * DI, pwbf + WOFF_IN(l), DM, 2 * DI);
        wprep_kernel<<<dim3(512/32, 512/32), 256>>>(
            dtW + (size_t)l * DI * DI, pwbf + WOFF_DT(l), DI, DI);
        wprep_kernel<<<dim3(256/32, 512/32), 256>>>(
            outW + (size_t)l * DI * DM, pwbf + WOFF_OUT(l), DI, DM);
    }
    wprep_kernel<<<dim3(256/32, 256/32), 256>>>(headW, pwbf + WOFF_HEAD, DM, NVOCAB);

    // 1) embedding
    embed_kernel<<<TT * DM / 256, 256>>>(bytes, embW, px, pxh);

    // 2) two mamba blocks
    for (int l = 0; l < 2; l++) {
        // x @ in_proj  (M=TT, N=1024, K=256)
        mma_gemm_kernel<<<dim3(1024/GBN, TT/GBM), 256>>>(
            pxh, DM, pwbf + WOFF_IN(l), DM, pxinz, 2 * DI, DM);
        // depthwise conv + silu
        conv_silu_kernel<<<TT * DI / 256, 256>>>(
            pxinz, cw + (size_t)l * DI * DCONV, cb + (size_t)l * DI, pxch);
        // xc @ dt_w  (N=512, K=512)
        mma_gemm_kernel<<<dim3(512/GBN, TT/GBM), 256>>>(
            pxch, DI, pwbf + WOFF_DT(l), DI, pdt, DI, DI);
        // xc @ x_proj[:, :16] -> Bmat (tiny, SIMT)
        gemm_small_kernel<64,16,32,4,1><<<dim3(1, TT/64), 256>>>(
            pxch, DI, xpW + (size_t)l * DI * 2 * DSTATE, 2 * DSTATE, pB, DSTATE, DI);
        // fused pointwise core
        mamba_ew_kernel<<<TT / EW_TOKS, 256>>>(
            pdt, pxch, pxinz, pB,
            Alog + (size_t)l * DI * DSTATE, dtb + (size_t)l * DI,
            Dp + (size_t)l * DI, puh);
        // u @ out_w  (N=256, K=512)
        mma_gemm_kernel<<<dim3(256/GBN, TT/GBM), 256>>>(
            puh, DI, pwbf + WOFF_OUT(l), DI, py2, DM, DI);
        // residual + rmsnorm
        rmsnorm_add_kernel<<<TT, 256>>>(px, pxh, py2, nw + (size_t)l * DM);
    }

    // 3) head + entropy  (N=256, K=256)
    mma_gemm_kernel<<<dim3(NVOCAB/GBN, TT/GBM), 256>>>(
        pxh, DM, pwbf + WOFF_HEAD, DM, plog, NVOCAB, DM);
    entropy_kernel<<<TT, 256>>>(plog, pent);

    // 4) boundaries
    boundary_kernel<<<BB, 256>>>(pent, ppstart, pnp, out + (size_t)TT * DM + TT);

    // 5) patch pooling
    pool_kernel<<<BB * SS, 256>>>(be, ppstart, pnp, out, out + (size_t)TT * DM);
}

// round 6
// speedup vs baseline: 3.3543x; 1.1266x over previous
#include <cuda_runtime.h>
#include <cuda_bf16.h>
#include <math.h>
#include <stdint.h>

// ---------------------------------------------------------------------------
// Problem constants
// ---------------------------------------------------------------------------
#define BB     8
#define SS     2048
#define TT     (BB*SS)
#define DM     256
#define DI     512
#define DSTATE 16
#define DCONV  4
#define NVOCAB 256
#define LOG_VOCAB_F 5.5451774444795623f
#define RMS_EPS 1.1920928955078125e-7f

typedef __nv_bfloat16 bf16;

// ---------------------------------------------------------------------------
// Scratch
// ---------------------------------------------------------------------------
__device__ float g_x    [TT * DM];        // residual stream fp32
__device__ bf16  g_xh   [TT * DM];        // residual stream bf16
__device__ bf16  g_xinzh[TT * 2 * DI];    // in_proj out (x_in | z) bf16
__device__ bf16  g_xch  [TT * DI];        // conv+silu out bf16
__device__ bf16  g_dth  [TT * DI];        // dt pre-activation bf16
__device__ float g_Bm   [TT * DSTATE];    // B matrix fp32
__device__ bf16  g_uh   [TT * DI];        // gated y bf16
__device__ float g_ent  [TT];
__device__ int   g_pstart[BB * SS];
__device__ int   g_np    [BB];

// bf16 transposed weights [N,K] row-major, packed
#define WOFF_IN(l)   ((size_t)(l) * 1024 * 256)
#define WOFF_DT(l)   (524288u  + (size_t)(l) * 512 * 512)
#define WOFF_OUT(l)  (1048576u + (size_t)(l) * 256 * 512)
#define WOFF_HEAD    (1310720u)
__device__ bf16 g_wbf[1376256];

// ---------------------------------------------------------------------------
// Weight prep, ALL weights in one launch. 1344 tiles of 32x32.
// ---------------------------------------------------------------------------
__global__ void wprep_all_kernel(const float* __restrict__ inW,
                                 const float* __restrict__ dtW,
                                 const float* __restrict__ outW,
                                 const float* __restrict__ headW,
                                 bf16* __restrict__ wout) {
    __shared__ float tile[32][33];
    int blk = blockIdx.x;
    const float* W; bf16* O; int K, N, t;
    if (blk < 512)       { int l = blk >> 8;        t = blk & 255;        W = inW  + (size_t)l*DM*2*DI; O = wout + WOFF_IN(l);  K = DM; N = 2*DI; }
    else if (blk < 1024) { int l = (blk-512) >> 8;  t = blk & 255;        W = dtW  + (size_t)l*DI*DI;   O = wout + WOFF_DT(l);  K = DI; N = DI; }
    else if (blk < 1280) { int l = (blk-1024) >> 7; t = (blk-1024) & 127; W = outW + (size_t)l*DI*DM;   O = wout + WOFF_OUT(l); K = DI; N = DM; }
    else                 { t = blk - 1280;          W = headW;            O = wout + WOFF_HEAD;         K = DM; N = NVOCAB; }
    int ncols = N >> 5;
    int nb = (t % ncols) * 32, kb = (t / ncols) * 32;
    int tx = threadIdx.x & 31, ty = threadIdx.x >> 5;
    #pragma unroll
    for (int r = ty; r < 32; r += 8)
        tile[r][tx] = W[(size_t)(kb + r) * N + nb + tx];
    __syncthreads();
    #pragma unroll
    for (int r = ty; r < 32; r += 8)
        O[(size_t)(nb + r) * K + kb + tx] = __float2bfloat16_rn(tile[tx][r]);
}

// ---------------------------------------------------------------------------
// Embedding lookup (fp32 + bf16)
// ---------------------------------------------------------------------------
__global__ void embed_kernel(const int* __restrict__ bytes,
                             const float* __restrict__ embW,
                             float* __restrict__ x, bf16* __restrict__ xh) {
    int idx = blockIdx.x * blockDim.x + threadIdx.x;
    int t = idx >> 8;
    int d = idx & 255;
    float v = embW[bytes[t] * DM + d];
    x[idx] = v;
    xh[idx] = __float2bfloat16_rn(v);
}

// ---------------------------------------------------------------------------
// mma helpers
// ---------------------------------------------------------------------------
__device__ __forceinline__ void cp_async16(void* smem, const void* gmem) {
    uint32_t s = (uint32_t)__cvta_generic_to_shared(smem);
    asm volatile("cp.async.cg.shared.global [%0], [%1], 16;" :: "r"(s), "l"(gmem));
}
__device__ __forceinline__ uint32_t ld32h(const bf16* p) {
    return *reinterpret_cast<const uint32_t*>(p);
}
__device__ __forceinline__ void mma16816(float* c, const uint32_t* a, const uint32_t* b) {
    asm volatile(
        "mma.sync.aligned.m16n8k16.row.col.f32.bf16.bf16.f32 "
        "{%0,%1,%2,%3},{%4,%5,%6,%7},{%8,%9},{%0,%1,%2,%3};"
        : "+f"(c[0]), "+f"(c[1]), "+f"(c[2]), "+f"(c[3])
        : "r"(a[0]), "r"(a[1]), "r"(a[2]), "r"(a[3]), "r"(b[0]), "r"(b[1]));
}
__device__ __forceinline__ uint32_t packbf(float a, float b) {
    __nv_bfloat162 h = __float22bfloat162_rn(make_float2(a, b));
    return *reinterpret_cast<uint32_t*>(&h);
}

// ---------------------------------------------------------------------------
// bf16-out tensor-core GEMM: C[M,N](bf16) = A[M,K](bf16) @ Bt[N,K]^T
// 128x64x32 tiles, 256 threads, cp.async double buffer. (in_proj, dt)
// ---------------------------------------------------------------------------
#define GBM 128
#define GBN 64
#define ASTR 40

__global__ void __launch_bounds__(256)
mma_gemm_bf16_kernel(const bf16* __restrict__ A, int lda,
                     const bf16* __restrict__ Bt, int ldb,
                     bf16* __restrict__ C, int ldc, int K) {
    __shared__ __align__(16) bf16 sA[2][GBM * ASTR];
    __shared__ __align__(16) bf16 sB[2][GBN * ASTR];

    const int tid  = threadIdx.x;
    const int lane = tid & 31;
    const int g    = lane >> 2;
    const int tg   = lane & 3;
    const int warp = tid >> 5;
    const int wm   = warp & 3;
    const int wn   = warp >> 2;
    const int mBase = wm * 32;
    const int nBase = wn * 32;
    const int rowBase = blockIdx.y * GBM;
    const int colBase = blockIdx.x * GBN;

    const int aRow = tid >> 2, aKc = tid & 3;
    const bf16* Ab = A + (size_t)rowBase * lda;
    const bf16* Bb = Bt + (size_t)colBase * ldb;

    float acc[2][4][4];
    #pragma unroll
    for (int mi = 0; mi < 2; mi++)
        #pragma unroll
        for (int ni = 0; ni < 4; ni++)
            #pragma unroll
            for (int c = 0; c < 4; c++) acc[mi][ni][c] = 0.f;

    const int nIter = K / 32;
    cp_async16(&sA[0][aRow * ASTR + aKc * 8],        Ab + (size_t)aRow * lda + aKc * 8);
    cp_async16(&sA[0][(aRow + 64) * ASTR + aKc * 8], Ab + (size_t)(aRow + 64) * lda + aKc * 8);
    cp_async16(&sB[0][aRow * ASTR + aKc * 8],        Bb + (size_t)aRow * ldb + aKc * 8);
    asm volatile("cp.async.commit_group;");

    for (int it = 0; it < nIter; ++it) {
        if (it + 1 < nIter) {
            int st = (it + 1) & 1;
            int k0 = (it + 1) * 32;
            cp_async16(&sA[st][aRow * ASTR + aKc * 8],        Ab + (size_t)aRow * lda + k0 + aKc * 8);
            cp_async16(&sA[st][(aRow + 64) * ASTR + aKc * 8], Ab + (size_t)(aRow + 64) * lda + k0 + aKc * 8);
            cp_async16(&sB[st][aRow * ASTR + aKc * 8],        Bb + (size_t)aRow * ldb + k0 + aKc * 8);
            asm volatile("cp.async.commit_group;");
            asm volatile("cp.async.wait_group 1;");
        } else {
            asm volatile("cp.async.wait_group 0;");
        }
        __syncthreads();

        const int buf = it & 1;
        const bf16* As = sA[buf];
        const bf16* Bs = sB[buf];

        #pragma unroll
        for (int ks = 0; ks < 2; ks++) {
            uint32_t af[2][4], bfr[4][2];
            #pragma unroll
            for (int mi = 0; mi < 2; mi++) {
                const bf16* ap = As + (mBase + mi * 16 + g) * ASTR + ks * 16 + tg * 2;
                af[mi][0] = ld32h(ap);
                af[mi][1] = ld32h(ap + 8 * ASTR);
                af[mi][2] = ld32h(ap + 8);
                af[mi][3] = ld32h(ap + 8 * ASTR + 8);
            }
            #pragma unroll
            for (int ni = 0; ni < 4; ni++) {
                const bf16* bp = Bs + (nBase + ni * 8 + g) * ASTR + ks * 16 + tg * 2;
                bfr[ni][0] = ld32h(bp);
                bfr[ni][1] = ld32h(bp + 8);
            }
            #pragma unroll
            for (int mi = 0; mi < 2; mi++)
                #pragma unroll
                for (int ni = 0; ni < 4; ni++)
                    mma16816(acc[mi][ni], af[mi], bfr[ni]);
        }
        __syncthreads();
    }

    #pragma unroll
    for (int mi = 0; mi < 2; mi++)
        #pragma unroll
        for (int ni = 0; ni < 4; ni++) {
            int row0 = rowBase + mBase + mi * 16 + g;
            int col  = colBase + nBase + ni * 8 + tg * 2;
            *reinterpret_cast<uint32_t*>(&C[(size_t)row0 * ldc + col]) =
                packbf(acc[mi][ni][0], acc[mi][ni][1]);
            *reinterpret_cast<uint32_t*>(&C[(size_t)(row0 + 8) * ldc + col]) =
                packbf(acc[mi][ni][2], acc[mi][ni][3]);
        }
}

// ---------------------------------------------------------------------------
// Wide-row fused GEMMs: BM=64, BN=256 (full row), BK=32, 512 threads,
// dynamic smem (51200B). Shared mainloop macro-style via inline function.
// acc[8][4] per thread; warp grid 4x4 (wm rows of 16, wn cols of 64).
// ---------------------------------------------------------------------------
#define FBM 64
#define FSA (FBM * ASTR)          // 2560 halves per stage
#define FSB (256 * ASTR)          // 10240 halves per stage

__device__ __forceinline__ void fused_mainloop(
    const bf16* __restrict__ A, int lda,
    const bf16* __restrict__ Bt, int ldb,
    int K, int rowBase, bf16* sm, float acc[8][4]) {

    bf16* sAb = sm;                 // [2][FSA]
    bf16* sBb = sm + 2 * FSA;       // [2][FSB]

    const int tid  = threadIdx.x;
    const int lane = tid & 31;
    const int g    = lane >> 2;
    const int tg   = lane & 3;
    const int warp = tid >> 5;
    const int wm   = warp & 3;
    const int wn   = warp >> 2;
    const int mBase = wm * 16;
    const int nBase = wn * 64;

    const bf16* Ab = A + (size_t)rowBase * lda;
    const int aRow = tid >> 2, aKc = tid & 3;        // tid<256 loads A
    const int b0Row = tid >> 2, b0Kc = tid & 3;      // chunk tid
    const int b1Row = (tid + 512) >> 2, b1Kc = tid & 3;

    const int nIter = K / 32;
    {
        if (tid < 256)
            cp_async16(&sAb[aRow * ASTR + aKc * 8], Ab + (size_t)aRow * lda + aKc * 8);
        cp_async16(&sBb[b0Row * ASTR + b0Kc * 8], Bt + (size_t)b0Row * ldb + b0Kc * 8);
        cp_async16(&sBb[b1Row * ASTR + b1Kc * 8], Bt + (size_t)b1Row * ldb + b1Kc * 8);
        asm volatile("cp.async.commit_group;");
    }

    for (int it = 0; it < nIter; ++it) {
        if (it + 1 < nIter) {
            int st = (it + 1) & 1;
            int k0 = (it + 1) * 32;
            if (tid < 256)
                cp_async16(&sAb[st * FSA + aRow * ASTR + aKc * 8],
                           Ab + (size_t)aRow * lda + k0 + aKc * 8);
            cp_async16(&sBb[st * FSB + b0Row * ASTR + b0Kc * 8],
                       Bt + (size_t)b0Row * ldb + k0 + b0Kc * 8);
            cp_async16(&sBb[st * FSB + b1Row * ASTR + b1Kc * 8],
                       Bt + (size_t)b1Row * ldb + k0 + b1Kc * 8);
            asm volatile("cp.async.commit_group;");
            asm volatile("cp.async.wait_group 1;");
        } else {
            asm volatile("cp.async.wait_group 0;");
        }
        __syncthreads();

        const int buf = it & 1;
        const bf16* As = sAb + buf * FSA;
        const bf16* Bs = sBb + buf * FSB;

        #pragma unroll
        for (int ks = 0; ks < 2; ks++) {
            uint32_t af[4], bfr[8][2];
            const bf16* ap = As + (mBase + g) * ASTR + ks * 16 + tg * 2;
            af[0] = ld32h(ap);
            af[1] = ld32h(ap + 8 * ASTR);
            af[2] = ld32h(ap + 8);
            af[3] = ld32h(ap + 8 * ASTR + 8);
            #pragma unroll
            for (int ni = 0; ni < 8; ni++) {
                const bf16* bp = Bs + (nBase + ni * 8 + g) * ASTR + ks * 16 + tg * 2;
                bfr[ni][0] = ld32h(bp);
                bfr[ni][1] = ld32h(bp + 8);
            }
            #pragma unroll
            for (int ni = 0; ni < 8; ni++)
                mma16816(acc[ni], af, bfr[ni]);
        }
        __syncthreads();
    }
}

// out_proj GEMM + residual + RMSNorm -> px (fp32) and pxh (bf16)
__global__ void __launch_bounds__(512)
gemm_rms_kernel(const bf16* __restrict__ A,     // puh [TT,DI]
                const bf16* __restrict__ Bt,    // out weights [256,512]
                float* __restrict__ x, bf16* __restrict__ xh,
                const float* __restrict__ nw) {
    extern __shared__ __align__(16) char dsm[];
    bf16* sm = (bf16*)dsm;
    float acc[8][4];
    #pragma unroll
    for (int ni = 0; ni < 8; ni++)
        #pragma unroll
        for (int c = 0; c < 4; c++) acc[ni][c] = 0.f;

    const int rowBase = blockIdx.x * FBM;
    fused_mainloop(A, DI, Bt, DI, DI, rowBase, sm, acc);

    const int tid  = threadIdx.x;
    const int lane = tid & 31;
    const int g    = lane >> 2;
    const int tg   = lane & 3;
    const int warp = tid >> 5;
    const int wm   = warp & 3;
    const int wn   = warp >> 2;
    const int r0   = wm * 16 + g;          // local row 0..63
    const int r1   = r0 + 8;
    const int t0   = rowBase + r0;
    const int t1   = rowBase + r1;

    // residual add, accumulate sum of squares
    float pA = 0.f, pB = 0.f;
    #pragma unroll
    for (int ni = 0; ni < 8; ni++) {
        int col = wn * 64 + ni * 8 + tg * 2;
        float2 x0 = *reinterpret_cast<const float2*>(&x[(size_t)t0 * DM + col]);
        float2 x1 = *reinterpret_cast<const float2*>(&x[(size_t)t1 * DM + col]);
        acc[ni][0] += x0.x; acc[ni][1] += x0.y;
        acc[ni][2] += x1.x; acc[ni][3] += x1.y;
        pA += acc[ni][0]*acc[ni][0] + acc[ni][1]*acc[ni][1];
        pB += acc[ni][2]*acc[ni][2] + acc[ni][3]*acc[ni][3];
    }
    pA += __shfl_xor_sync(0xffffffffu, pA, 1);
    pA += __shfl_xor_sync(0xffffffffu, pA, 2);
    pB += __shfl_xor_sync(0xffffffffu, pB, 1);
    pB += __shfl_xor_sync(0xffffffffu, pB, 2);

    float* sred = (float*)dsm;     // [64][4] partials then [64] scales at 256
    __syncthreads();               // mainloop smem no longer needed
    if (tg == 0) { sred[r0 * 4 + wn] = pA; sred[r1 * 4 + wn] = pB; }
    __syncthreads();
    if (tid < 64) {
        float s = sred[tid*4] + sred[tid*4+1] + sred[tid*4+2] + sred[tid*4+3];
        sred[256 + tid] = rsqrtf(s * (1.f / DM) + RMS_EPS);
    }
    __syncthreads();
    float sc0 = sred[256 + r0];
    float sc1 = sred[256 + r1];

    #pragma unroll
    for (int ni = 0; ni < 8; ni++) {
        int col = wn * 64 + ni * 8 + tg * 2;
        float2 w = *reinterpret_cast<const float2*>(&nw[col]);
        float o0 = acc[ni][0] * sc0 * w.x, o1 = acc[ni][1] * sc0 * w.y;
        float o2 = acc[ni][2] * sc1 * w.x, o3 = acc[ni][3] * sc1 * w.y;
        *reinterpret_cast<float2*>(&x[(size_t)t0 * DM + col]) = make_float2(o0, o1);
        *reinterpret_cast<float2*>(&x[(size_t)t1 * DM + col]) = make_float2(o2, o3);
        *reinterpret_cast<uint32_t*>(&xh[(size_t)t0 * DM + col]) = packbf(o0, o1);
        *reinterpret_cast<uint32_t*>(&xh[(size_t)t1 * DM + col]) = packbf(o2, o3);
    }
}

// head GEMM + softmax entropy -> ent[TT]
__global__ void __launch_bounds__(512)
gemm_ent_kernel(const bf16* __restrict__ A,     // pxh [TT,DM]
                const bf16* __restrict__ Bt,    // head weights [256,256]
                float* __restrict__ ent) {
    extern __shared__ __align__(16) char dsm[];
    bf16* sm = (bf16*)dsm;
    float acc[8][4];
    #pragma unroll
    for (int ni = 0; ni < 8; ni++)
        #pragma unroll
        for (int c = 0; c < 4; c++) acc[ni][c] = 0.f;

    const int rowBase = blockIdx.x * FBM;
    fused_mainloop(A, DM, Bt, DM, DM, rowBase, sm, acc);

    const int tid  = threadIdx.x;
    const int lane = tid & 31;
    const int g    = lane >> 2;
    const int tg   = lane & 3;
    const int warp = tid >> 5;
    const int wm   = warp & 3;
    const int wn   = warp >> 2;
    const int r0   = wm * 16 + g;
    const int r1   = r0 + 8;

    // pass 1: row max
    float mA = -1e30f, mB = -1e30f;
    #pragma unroll
    for (int ni = 0; ni < 8; ni++) {
        mA = fmaxf(mA, fmaxf(acc[ni][0], acc[ni][1]));
        mB = fmaxf(mB, fmaxf(acc[ni][2], acc[ni][3]));
    }
    mA = fmaxf(mA, __shfl_xor_sync(0xffffffffu, mA, 1));
    mA = fmaxf(mA, __shfl_xor_sync(0xffffffffu, mA, 2));
    mB = fmaxf(mB, __shfl_xor_sync(0xffffffffu, mB, 1));
    mB = fmaxf(mB, __shfl_xor_sync(0xffffffffu, mB, 2));

    float* sred = (float*)dsm;     // [64][4], row max at 256, Z at 320..575, S...
    __syncthreads();
    if (tg == 0) { sred[r0 * 4 + wn] = mA; sred[r1 * 4 + wn] = mB; }
    __syncthreads();
    if (tid < 64)
        sred[256 + tid] = fmaxf(fmaxf(sred[tid*4], sred[tid*4+1]),
                                fmaxf(sred[tid*4+2], sred[tid*4+3]));
    __syncthreads();
    float rm0 = sred[256 + r0];
    float rm1 = sred[256 + r1];
    __syncthreads();

    // pass 2: Z = sum e, S = sum e*(l-m)
    float zA = 0.f, sAc = 0.f, zB = 0.f, sBc = 0.f;
    #pragma unroll
    for (int ni = 0; ni < 8; ni++) {
        float d0 = acc[ni][0] - rm0, d1 = acc[ni][1] - rm0;
        float d2 = acc[ni][2] - rm1, d3 = acc[ni][3] - rm1;
        float e0 = expf(d0), e1 = expf(d1), e2 = expf(d2), e3 = expf(d3);
        zA += e0 + e1;  sAc += e0 * d0 + e1 * d1;
        zB += e2 + e3;  sBc += e2 * d2 + e3 * d3;
    }
    zA  += __shfl_xor_sync(0xffffffffu, zA, 1);
    zA  += __shfl_xor_sync(0xffffffffu, zA, 2);
    sAc += __shfl_xor_sync(0xffffffffu, sAc, 1);
    sAc += __shfl_xor_sync(0xffffffffu, sAc, 2);
    zB  += __shfl_xor_sync(0xffffffffu, zB, 1);
    zB  += __shfl_xor_sync(0xffffffffu, zB, 2);
    sBc += __shfl_xor_sync(0xffffffffu, sBc, 1);
    sBc += __shfl_xor_sync(0xffffffffu, sBc, 2);

    if (tg == 0) {
        sred[r0 * 4 + wn] = zA;        sred[r1 * 4 + wn] = zB;
        sred[320 + r0 * 4 + wn] = sAc; sred[320 + r1 * 4 + wn] = sBc;
    }
    __syncthreads();
    if (tid < 64) {
        float Z = sred[tid*4] + sred[tid*4+1] + sred[tid*4+2] + sred[tid*4+3];
        float S = sred[320+tid*4] + sred[320+tid*4+1] + sred[320+tid*4+2] + sred[320+tid*4+3];
        ent[rowBase + tid] = (logf(Z) - S / Z) / LOG_VOCAB_F;
    }
}

// ---------------------------------------------------------------------------
// Small SIMT GEMM (bf16 A, fp32 W): x_proj B half (N=16, K=512)
// ---------------------------------------------------------------------------
template<int BM, int BN, int BK, int TM, int TN>
__global__ void gemm_small_kernel(const bf16* __restrict__ A, int lda,
                                  const float* __restrict__ W, int ldw,
                                  float* __restrict__ C, int ldc, int K) {
    __shared__ float As[BK][BM + 4];
    __shared__ float Ws[BK][BN];

    const int tid = threadIdx.x;
    const int nTx = BN / TN;
    const int tx  = tid % nTx;
    const int ty  = tid / nTx;
    const int rowBase = blockIdx.y * BM;
    const int colBase = blockIdx.x * BN;

    float acc[TM][TN];
    #pragma unroll
    for (int i = 0; i < TM; i++)
        #pragma unroll
        for (int j = 0; j < TN; j++) acc[i][j] = 0.f;

    for (int k0 = 0; k0 < K; k0 += BK) {
        for (int i = tid; i < BM * BK; i += 256) {
            int m  = i / BK;
            int kk = i % BK;
            As[kk][m] = __bfloat162float(A[(size_t)(rowBase + m) * lda + k0 + kk]);
        }
        for (int i = tid; i < BK * BN; i += 256) {
            int kk = i / BN;
            int n  = i % BN;
            Ws[kk][n] = W[(size_t)(k0 + kk) * ldw + colBase + n];
        }
        __syncthreads();
        #pragma unroll
        for (int kk = 0; kk < BK; kk++) {
            float a[TM], b[TN];
            #pragma unroll
            for (int i = 0; i < TM; i++) a[i] = As[kk][ty * TM + i];
            #pragma unroll
            for (int j = 0; j < TN; j++) b[j] = Ws[kk][tx * TN + j];
            #pragma unroll
            for (int i = 0; i < TM; i++)
                #pragma unroll
                for (int j = 0; j < TN; j++)
                    acc[i][j] = fmaf(a[i], b[j], acc[i][j]);
        }
        __syncthreads();
    }
    #pragma unroll
    for (int i = 0; i < TM; i++)
        #pragma unroll
        for (int j = 0; j < TN; j++)
            C[(size_t)(rowBase + ty * TM + i) * ldc + colBase + tx * TN + j] = acc[i][j];
}

// ---------------------------------------------------------------------------
// Causal depthwise conv + bias + silu (bf16 in/out)
// ---------------------------------------------------------------------------
__global__ void conv_silu_kernel(const bf16* __restrict__ xinzh,
                                 const float* __restrict__ cw,
                                 const float* __restrict__ cb,
                                 bf16* __restrict__ xch) {
    int idx = blockIdx.x * blockDim.x + threadIdx.x;
    int t = idx / DI;
    int d = idx - t * DI;
    int b = t / SS;
    int s = t - b * SS;

    float acc = cb[d];
    #pragma unroll
    for (int k = 0; k < DCONV; k++) {
        int ss = s - (DCONV - 1) + k;
        if (ss >= 0)
            acc = fmaf(cw[d * DCONV + k],
                       __bfloat162float(xinzh[(size_t)(b * SS + ss) * (2 * DI) + d]), acc);
    }
    float v = acc / (1.f + expf(-acc));
    xch[idx] = __float2bfloat16_rn(v);
}

// ---------------------------------------------------------------------------
// Fused Mamba pointwise core
// ---------------------------------------------------------------------------
#define EW_TOKS 8
__global__ void mamba_ew_kernel(const bf16* __restrict__ dth,
                                const bf16* __restrict__ xch,
                                const bf16* __restrict__ xinzh,
                                const float* __restrict__ Bmat,
                                const float* __restrict__ Alog,
                                const float* __restrict__ dtb,
                                const float* __restrict__ Dp,
                                bf16* __restrict__ uh) {
    __shared__ float negAT[DSTATE][DI];
    __shared__ float sdtb[DI];
    __shared__ float sD[DI];
    __shared__ float sB[DSTATE];

    const int tid = threadIdx.x;
    for (int i = tid; i < DI * DSTATE; i += 256) {
        int d = i / DSTATE, n = i % DSTATE;
        negAT[n][d] = -expf(Alog[i]);
    }
    for (int i = tid; i < DI; i += 256) { sdtb[i] = dtb[i]; sD[i] = Dp[i]; }
    __syncthreads();

    for (int tok = 0; tok < EW_TOKS; tok++) {
        int t = blockIdx.x * EW_TOKS + tok;
        if (tid < DSTATE) sB[tid] = Bmat[t * DSTATE + tid];
        __syncthreads();

        #pragma unroll
        for (int rep = 0; rep < 2; rep++) {
            int d = tid + rep * 256;
            float v   = __bfloat162float(dth[(size_t)t * DI + d]) + sdtb[d];
            float dtv = fmaxf(v, 0.f) + log1pf(expf(-fabsf(v)));
            float xcv = __bfloat162float(xch[(size_t)t * DI + d]);
            float accn = 0.f;
            #pragma unroll
            for (int n = 0; n < DSTATE; n++)
                accn = fmaf(expf(negAT[n][d] * dtv), sB[n], accn);
            float yv = dtv * xcv * accn + sD[d] * xcv;
            float zv = __bfloat162float(xinzh[(size_t)t * (2 * DI) + DI + d]);
            uh[(size_t)t * DI + d] = __float2bfloat16_rn(yv * (zv / (1.f + expf(-zv))));
        }
        __syncthreads();
    }
}

// ---------------------------------------------------------------------------
// Sequential boundary automaton per batch row
// ---------------------------------------------------------------------------
__global__ void boundary_kernel(const float* __restrict__ ent,
                                int* __restrict__ pstart,
                                int* __restrict__ np,
                                float* __restrict__ out_b2p) {
    __shared__ float se[SS];
    int b = blockIdx.x;
    for (int i = threadIdx.x; i < SS; i += blockDim.x)
        se[i] = ent[b * SS + i];
    __syncthreads();

    if (threadIdx.x == 0) {
        int size = 1;
        int p = 0;
        pstart[b * SS + 0] = 0;
        out_b2p[b * SS + 0] = 0.f;
        for (int s = 1; s < SS; s++) {
            float e = se[s];
            bool nb = (e > 0.5f) || (size >= 8);
            if (nb) { p++; pstart[b * SS + p] = s; size = 1; }
            else    { size++; }
            out_b2p[b * SS + s] = (float)p;
        }
        np[b] = p + 1;
    }
}

// ---------------------------------------------------------------------------
// Patch mean pooling
// ---------------------------------------------------------------------------
__global__ void pool_kernel(const float* __restrict__ be,
                            const int* __restrict__ pstart,
                            const int* __restrict__ np,
                            float* __restrict__ out_emb,
                            float* __restrict__ out_len) {
    int blk = blockIdx.x;
    int b = blk / SS;
    int p = blk - b * SS;
    int d = threadIdx.x;
    int npb = np[b];

    if (p < npb) {
        int s0 = pstart[b * SS + p];
        int s1 = (p + 1 < npb) ? pstart[b * SS + p + 1] : SS;
        float sum = 0.f;
        for (int s = s0; s < s1; s++)
            sum += be[(size_t)(b * SS + s) * DM + d];
        out_emb[(size_t)blk * DM + d] = sum / (float)(s1 - s0);
        if (d == 0) out_len[blk] = (float)(s1 - s0);
    } else {
        out_emb[(size_t)blk * DM + d] = 0.f;
        if (d == 0) out_len[blk] = 0.f;
    }
}

// ---------------------------------------------------------------------------
// Launch
// ---------------------------------------------------------------------------
#define FUSED_SMEM 51200

extern "C" void kernel_launch(void* const* d_in, const int* in_sizes, int n_in,
                              void* d_out, int out_size) {
    const int*   bytes = (const int*)  d_in[0];
    const float* be    = (const float*)d_in[1];
    const float* embW  = (const float*)d_in[2];
    const float* inW   = (const float*)d_in[3];
    const float* cw    = (const float*)d_in[4];
    const float* cb    = (const float*)d_in[5];
    const float* xpW   = (const float*)d_in[6];
    const float* dtW   = (const float*)d_in[7];
    const float* dtb   = (const float*)d_in[8];
    const float* Alog  = (const float*)d_in[9];
    const float* Dp    = (const float*)d_in[10];
    const float* outW  = (const float*)d_in[11];
    const float* nw    = (const float*)d_in[12];
    const float* headW = (const float*)d_in[13];
    float* out = (float*)d_out;

    static float *px=nullptr, *pB, *pent;
    static bf16 *pxh, *pxinzh, *pxch, *pdth, *puh, *pwbf;
    static int *ppstart, *pnp;
    if (!px) {
        cudaGetSymbolAddress((void**)&px,     g_x);
        cudaGetSymbolAddress((void**)&pxh,    g_xh);
        cudaGetSymbolAddress((void**)&pxinzh, g_xinzh);
        cudaGetSymbolAddress((void**)&pxch,   g_xch);
        cudaGetSymbolAddress((void**)&pdth,   g_dth);
        cudaGetSymbolAddress((void**)&pB,     g_Bm);
        cudaGetSymbolAddress((void**)&puh,    g_uh);
        cudaGetSymbolAddress((void**)&pent,   g_ent);
        cudaGetSymbolAddress((void**)&pwbf,   g_wbf);
        cudaGetSymbolAddress((void**)&ppstart,g_pstart);
        cudaGetSymbolAddress((void**)&pnp,    g_np);
        cudaFuncSetAttribute(gemm_rms_kernel,
            cudaFuncAttributeMaxDynamicSharedMemorySize, FUSED_SMEM);
        cudaFuncSetAttribute(gemm_ent_kernel,
            cudaFuncAttributeMaxDynamicSharedMemorySize, FUSED_SMEM);
    }

    // 0) weight prep (single launch)
    wprep_all_kernel<<<1344, 256>>>(inW, dtW, outW, headW, pwbf);

    // 1) embedding
    embed_kernel<<<TT * DM / 256, 256>>>(bytes, embW, px, pxh);

    // 2) two mamba blocks
    for (int l = 0; l < 2; l++) {
        // x @ in_proj -> xinz bf16  (N=1024, K=256)
        mma_gemm_bf16_kernel<<<dim3(1024/GBN, TT/GBM), 256>>>(
            pxh, DM, pwbf + WOFF_IN(l), DM, pxinzh, 2 * DI, DM);
        // depthwise conv + silu
        conv_silu_kernel<<<TT * DI / 256, 256>>>(
            pxinzh, cw + (size_t)l * DI * DCONV, cb + (size_t)l * DI, pxch);
        // xc @ dt_w -> dt bf16  (N=512, K=512)
        mma_gemm_bf16_kernel<<<dim3(512/GBN, TT/GBM), 256>>>(
            pxch, DI, pwbf + WOFF_DT(l), DI, pdth, DI, DI);
        // xc @ x_proj[:, :16] -> Bmat
        gemm_small_kernel<64,16,32,4,1><<<dim3(1, TT/64), 256>>>(
            pxch, DI, xpW + (size_t)l * DI * 2 * DSTATE, 2 * DSTATE, pB, DSTATE, DI);
        // fused pointwise core
        mamba_ew_kernel<<<TT / EW_TOKS, 256>>>(
            pdth, pxch, pxinzh, pB,
            Alog + (size_t)l * DI * DSTATE, dtb + (size_t)l * DI,
            Dp + (size_t)l * DI, puh);
        // u @ out_w + residual + rmsnorm (fused)
        gemm_rms_kernel<<<TT / FBM, 512, FUSED_SMEM>>>(
            puh, pwbf + WOFF_OUT(l), px, pxh, nw + (size_t)l * DM);
    }

    // 3) head + entropy (fused)
    gemm_ent_kernel<<<TT / FBM, 512, FUSED_SMEM>>>(pxh, pwbf + WOFF_HEAD, pent);

    // 4) boundaries
    boundary_kernel<<<BB, 256>>>(pent, ppstart, pnp, out + (size_t)TT * DM + TT);

    // 5) patch pooling
    pool_kernel<<<BB * SS, 256>>>(be, ppstart, pnp, out, out + (size_t)TT * DM);
}